// round 8
// baseline (speedup 1.0000x reference)
#include <cuda_runtime.h>

#define BB 16
#define LL 192
#define EE 128
#define TT 25
#define NI (LL - TT - 1)            // 166
#define OUT_L (TT + 1 + NI * LL)    // 31898
#define E4 (EE / 4)                 // 32 float4 per row
#define TPB 256
#define WARPS (TPB / 32)            // 8
#define L_RANGE 16                  // l-rows per CTA
#define LSPLITS (LL / L_RANGE)      // 12
#define NPASS (L_RANGE / WARPS)     // 2  -> 8 s-regs/thread
#define I_PER_BLK 12
#define ICH ((NI + I_PER_BLK - 1) / I_PER_BLK)  // 14  (R5 optimum)

// Precomputed softmax weight s0[b,l,e] (2-way softmax collapsed; s1 = 1-s0).
// 1.5 MB -> L2-resident.
__device__ float g_s0[BB * LL * EE];

// ---------------------------------------------------------------------------
// Kernel 1: s0 = sigmoid(x*(W0-W1) + (b0-b1))
// Triggers programmatic completion so the dependent kernel can ramp early.
// ---------------------------------------------------------------------------
__global__ void __launch_bounds__(512, 2)
s0_kernel(const float* __restrict__ x,
          const float* __restrict__ W,
          const float* __restrict__ bv) {
    const float dW = W[0] - W[1];
    const float db = bv[0] - bv[1];
    int n0 = (blockIdx.x * 512 + threadIdx.x) * 2;
    #pragma unroll
    for (int k = 0; k < 2; k++) {
        int n = n0 + k;
        float4 xv = reinterpret_cast<const float4*>(x)[n];
        float4 s;
        s.x = 1.0f / (1.0f + __expf(-fmaf(xv.x, dW, db)));
        s.y = 1.0f / (1.0f + __expf(-fmaf(xv.y, dW, db)));
        s.z = 1.0f / (1.0f + __expf(-fmaf(xv.z, dW, db)));
        s.w = 1.0f / (1.0f + __expf(-fmaf(xv.w, dW, db)));
        reinterpret_cast<float4*>(g_s0)[n] = s;
    }
    cudaTriggerProgrammaticLaunchCompletion();
}

// ---------------------------------------------------------------------------
// Kernel 2 (main): blocks[b,i,l,e] = xp + s0[b,l,e]*(xi-xp)
//   xi = x[b, i+T+1, e], xp = x[b, i+1, e]
// Launched with PDL: prologue (head copy, address setup) overlaps s0_kernel;
// cudaGridDependencySynchronize() gates only the g_s0 reads.
// Grid (14, 12, 16) = 2688 CTAs (R5 optimum), launch_bounds(256,6).
// Pointer-increment addressing, 2-stage xi/xp prefetch,
// warp-coalesced 512B streaming STG.128 rows.
// ---------------------------------------------------------------------------
__global__ void __launch_bounds__(TPB, 6)
blocks_kernel(const float* __restrict__ x, float* __restrict__ out) {
    const int b  = blockIdx.z;
    const int l0 = blockIdx.y * L_RANGE;
    const int e4 = threadIdx.x & (E4 - 1);     // 0..31, contiguous in warp
    const int w  = threadIdx.x >> 5;           // 0..7, constant in warp

    const float4* xb  = reinterpret_cast<const float4*>(x) + b * (LL * E4);
    const float4* s0b = reinterpret_cast<const float4*>(g_s0) + b * (LL * E4);
    float4* o4 = reinterpret_cast<float4*>(out);

    // Head copy: out[b, 0:26, :] = x[b, 0:26, :] (one CTA per batch).
    // Independent of g_s0 -> runs while s0_kernel is still in flight.
    if (blockIdx.x == 0 && blockIdx.y == 0) {
        const size_t ob = (size_t)b * (OUT_L * E4);
        #pragma unroll
        for (int k = threadIdx.x; k < (TT + 1) * E4; k += TPB)
            __stcs(o4 + ob + k, xb[k]);
    }

    const int i0 = blockIdx.x * I_PER_BLK;
    const int iend = min(i0 + I_PER_BLK, NI);
    if (i0 >= iend) return;
    const int n_iter = iend - i0;

    // Address setup (also independent of g_s0)
    const float4* pxi = xb + (i0 + TT + 1) * E4 + e4;
    const float4* pxp = xb + (i0 + 1) * E4 + e4;
    float4* po = o4 + ((size_t)b * OUT_L + (TT + 1) + (size_t)i0 * LL + l0 + w) * E4 + e4;

    // Wait for s0_kernel's results to be visible, then load s-values.
    cudaGridDependencySynchronize();

    float4 s[NPASS];
    #pragma unroll
    for (int p = 0; p < NPASS; p++)
        s[p] = s0b[(l0 + w + p * WARPS) * E4 + e4];

    // 2-stage pipeline on xi/xp
    float4 xi = *pxi;
    float4 xp = *pxp;

    for (int it = 0; it < n_iter; it++) {
        float4 nxi, nxp;
        if (it + 1 < n_iter) {
            nxi = pxi[E4];
            nxp = pxp[E4];
        }
        pxi += E4; pxp += E4;

        float4 d;
        d.x = xi.x - xp.x; d.y = xi.y - xp.y;
        d.z = xi.z - xp.z; d.w = xi.w - xp.w;

        #pragma unroll
        for (int p = 0; p < NPASS; p++) {
            float4 o;
            o.x = fmaf(s[p].x, d.x, xp.x);
            o.y = fmaf(s[p].y, d.y, xp.y);
            o.z = fmaf(s[p].z, d.z, xp.z);
            o.w = fmaf(s[p].w, d.w, xp.w);
            // write-once output: streaming store, evict-first in L2
            __stcs(po + p * (WARPS * E4), o);
        }
        po += (size_t)(LL * E4);   // next i: advance one L-block

        xi = nxi; xp = nxp;
    }
}

// ---------------------------------------------------------------------------
extern "C" void kernel_launch(void* const* d_in, const int* in_sizes, int n_in,
                              void* d_out, int out_size) {
    const float* x  = (const float*)d_in[0];  // (16,192,128) f32
    const float* W  = (const float*)d_in[1];  // (2,1) f32
    const float* bv = (const float*)d_in[2];  // (2,) f32
    float* out = (float*)d_out;               // (16,31898,128) f32

    s0_kernel<<<96, 512>>>(x, W, bv);         // 96*512*2 f4 = 98304

    // Dependent launch with programmatic stream serialization (PDL):
    // blocks_kernel ramps while s0_kernel finishes.
    cudaLaunchConfig_t cfg = {};
    cfg.gridDim  = dim3(ICH, LSPLITS, BB);    // 14 x 12 x 16 = 2688 CTAs
    cfg.blockDim = dim3(TPB, 1, 1);
    cfg.dynamicSmemBytes = 0;
    cfg.stream = 0;
    cudaLaunchAttribute attr[1];
    attr[0].id = cudaLaunchAttributeProgrammaticStreamSerialization;
    attr[0].val.programmaticStreamSerializationAllowed = 1;
    cfg.attrs = attr;
    cfg.numAttrs = 1;
    cudaLaunchKernelEx(&cfg, blocks_kernel, x, out);
}

// round 9
// speedup vs baseline: 1.0483x; 1.0483x over previous
#include <cuda_runtime.h>

#define BB 16
#define LL 192
#define EE 128
#define TT 25
#define NI (LL - TT - 1)            // 166
#define OUT_L (TT + 1 + NI * LL)    // 31898
#define E4 (EE / 4)                 // 32 float4 per row
#define TPB 256
#define WARPS (TPB / 32)            // 8
#define L_RANGE 16                  // l-rows per CTA
#define LSPLITS (LL / L_RANGE)      // 12
#define NPASS (L_RANGE / WARPS)     // 2  -> 8 s-regs/thread
#define I_PER_BLK 12
#define ICH ((NI + I_PER_BLK - 1) / I_PER_BLK)  // 14  (R5 optimum)

// sigmoid(z) = 0.5*tanh(z/2) + 0.5  -> single MUFU op (tanh.approx.f32)
__device__ __forceinline__ float fast_sigmoid_half(float zhalf) {
    float t;
    asm("tanh.approx.f32 %0, %1;" : "=f"(t) : "f"(zhalf));
    return fmaf(0.5f, t, 0.5f);
}

// ---------------------------------------------------------------------------
// Single fused kernel: blocks[b,i,l,e] = xp + s0[b,l,e]*(xi-xp)
//   s0 = sigmoid(x*(W0-W1) + (b0-b1))  (2-way softmax collapsed; s1 = 1-s0)
//   xi = x[b, i+T+1, e], xp = x[b, i+1, e]
// Per-CTA sigmoid prologue uses tanh.approx (1 MUFU/elem, 8 elems/thread):
// chip-wide ~1.1us, cheaper than the 3.3us split-kernel overhead it replaces.
// Grid (14,12,16) = 2688 CTAs (R5 optimum), launch_bounds(256,6).
// Pointer-increment addressing, 2-stage xi/xp prefetch,
// warp-coalesced 512B streaming STG.128 rows.
// ---------------------------------------------------------------------------
__global__ void __launch_bounds__(TPB, 6)
fused_kernel(const float* __restrict__ x,
             const float* __restrict__ W,
             const float* __restrict__ bv,
             float* __restrict__ out) {
    const int b  = blockIdx.z;
    const int l0 = blockIdx.y * L_RANGE;
    const int e4 = threadIdx.x & (E4 - 1);     // 0..31, contiguous in warp
    const int w  = threadIdx.x >> 5;           // 0..7, constant in warp

    const float4* xb = reinterpret_cast<const float4*>(x) + b * (LL * E4);
    float4* o4 = reinterpret_cast<float4*>(out);

    // Head copy: out[b, 0:26, :] = x[b, 0:26, :] (one CTA per batch)
    if (blockIdx.x == 0 && blockIdx.y == 0) {
        const size_t ob = (size_t)b * (OUT_L * E4);
        #pragma unroll
        for (int k = threadIdx.x; k < (TT + 1) * E4; k += TPB)
            __stcs(o4 + ob + k, xb[k]);
    }

    // Inline sigmoid for this thread's 2 s-float4 (i-invariant within CTA).
    // Fold the /2 of tanh-sigmoid into the affine: zhalf = x*dW2 + db2.
    const float dW2 = 0.5f * (W[0] - W[1]);
    const float db2 = 0.5f * (bv[0] - bv[1]);
    float4 s[NPASS];
    #pragma unroll
    for (int p = 0; p < NPASS; p++) {
        float4 xv = xb[(l0 + w + p * WARPS) * E4 + e4];
        s[p].x = fast_sigmoid_half(fmaf(xv.x, dW2, db2));
        s[p].y = fast_sigmoid_half(fmaf(xv.y, dW2, db2));
        s[p].z = fast_sigmoid_half(fmaf(xv.z, dW2, db2));
        s[p].w = fast_sigmoid_half(fmaf(xv.w, dW2, db2));
    }

    const int i0 = blockIdx.x * I_PER_BLK;
    const int iend = min(i0 + I_PER_BLK, NI);
    if (i0 >= iend) return;
    const int n_iter = iend - i0;

    // Hot-loop pointers: advance by constants per i (no per-i multiplies)
    const float4* pxi = xb + (i0 + TT + 1) * E4 + e4;
    const float4* pxp = xb + (i0 + 1) * E4 + e4;
    float4* po = o4 + ((size_t)b * OUT_L + (TT + 1) + (size_t)i0 * LL + l0 + w) * E4 + e4;

    // 2-stage pipeline on xi/xp
    float4 xi = *pxi;
    float4 xp = *pxp;

    for (int it = 0; it < n_iter; it++) {
        float4 nxi, nxp;
        if (it + 1 < n_iter) {
            nxi = pxi[E4];
            nxp = pxp[E4];
        }
        pxi += E4; pxp += E4;

        float4 d;
        d.x = xi.x - xp.x; d.y = xi.y - xp.y;
        d.z = xi.z - xp.z; d.w = xi.w - xp.w;

        #pragma unroll
        for (int p = 0; p < NPASS; p++) {
            float4 o;
            o.x = fmaf(s[p].x, d.x, xp.x);
            o.y = fmaf(s[p].y, d.y, xp.y);
            o.z = fmaf(s[p].z, d.z, xp.z);
            o.w = fmaf(s[p].w, d.w, xp.w);
            // write-once output: streaming store, evict-first in L2
            __stcs(po + p * (WARPS * E4), o);
        }
        po += (size_t)(LL * E4);   // next i: advance one L-block

        xi = nxi; xp = nxp;
    }
}

// ---------------------------------------------------------------------------
extern "C" void kernel_launch(void* const* d_in, const int* in_sizes, int n_in,
                              void* d_out, int out_size) {
    const float* x  = (const float*)d_in[0];  // (16,192,128) f32
    const float* W  = (const float*)d_in[1];  // (2,1) f32
    const float* bv = (const float*)d_in[2];  // (2,) f32
    float* out = (float*)d_out;               // (16,31898,128) f32

    dim3 grid(ICH, LSPLITS, BB);   // 14 x 12 x 16 = 2688 CTAs
    fused_kernel<<<grid, TPB>>>(x, W, bv, out);
}